// round 13
// baseline (speedup 1.0000x reference)
#include <cuda_runtime.h>
#include <cstdint>

#define BB 4
#define NN 8192
#define NP 2048
#define CC 64
#define NS 32
#define R2 0.01f
#define NSLOT 33
#define GPB (NP * NSLOT)   // 67584 group-slots per batch
#define SEGS 2             // point-dimension split for bq parallelism

// Scratch (no cudaMalloc allowed)
__device__ float g_featT[BB * NN * CC];          // features transposed to (B, N, C)
__device__ int   g_pidx[BB * NP * SEGS * NS];    // per-segment partial neighbor lists
__device__ int   g_pcnt[BB * NP * SEGS];         // per-segment counts (clamped to NS)

typedef unsigned long long u64;

// ---------------- packed f32x2 helpers ----------------
__device__ __forceinline__ u64 pk2(float lo, float hi) {
    u64 r; asm("mov.b64 %0, {%1, %2};" : "=l"(r) : "f"(lo), "f"(hi)); return r;
}
__device__ __forceinline__ void upk2(u64 v, float& lo, float& hi) {
    asm("mov.b64 {%0, %1}, %2;" : "=f"(lo), "=f"(hi) : "l"(v));
}
__device__ __forceinline__ u64 addx2(u64 a, u64 b) {
    u64 r; asm("add.rn.f32x2 %0, %1, %2;" : "=l"(r) : "l"(a), "l"(b)); return r;
}
__device__ __forceinline__ u64 mulx2(u64 a, u64 b) {
    u64 r; asm("mul.rn.f32x2 %0, %1, %2;" : "=l"(r) : "l"(a), "l"(b)); return r;
}
__device__ __forceinline__ u64 fmax2(u64 a, u64 b, u64 c) {
    u64 r; asm("fma.rn.f32x2 %0, %1, %2, %3;" : "=l"(r) : "l"(a), "l"(b), "l"(c)); return r;
}

#define BQ_M 4
#define BQ_WARPS 8
#define BQ_CPB (BQ_WARPS * BQ_M)   // 32 centroids per block
#define TILE_PTS 1024
#define TILE_PAIRS 512
#define SEG_TILES ((NN / TILE_PTS) / SEGS)          // 4 tiles per segment
#define NBQ ((BB * NP / BQ_CPB) * SEGS)             // 512 bq blocks
#define NTR (BB * (NN / 64))                        // 512 transpose blocks

__device__ __forceinline__ int swz(int p) {        // bank swizzle for u64 pair index
    return (p & ~15) | ((p ^ (p >> 4)) & 15);
}

// ---------------- fused K1: ball query blocks + transpose blocks ----------------
__global__ __launch_bounds__(256) void fused_kernel(const float* __restrict__ xyz,
                                                    const float* __restrict__ new_xyz,
                                                    const float* __restrict__ feat) {
    __shared__ __align__(16) char smem_raw[16640];   // max(bq 16384, transpose 16640)

    if (blockIdx.x < NBQ) {
        // ---- ball query part: 8 warps, 4 centroids/warp, one point segment ----
        u64* sx = (u64*)smem_raw;
        u64* sy = sx + TILE_PAIRS;
        u64* sz = sy + TILE_PAIRS;
        int (*slist)[NS] = (int(*)[NS])(smem_raw + 3 * TILE_PAIRS * 8);

        int tid    = threadIdx.x;
        int warpId = tid >> 5;
        int lane   = tid & 31;
        int cg     = blockIdx.x >> 1;          // centroid-group id (0..255)
        int seg    = blockIdx.x & 1;           // point segment (0..1)
        int cbase  = cg * BQ_CPB + warpId * BQ_M;
        int b      = (cg * BQ_CPB) / NP;       // uniform per block

        u64 qx2[BQ_M], qy2[BQ_M], qz2[BQ_M];
        int cnt[BQ_M];
        #pragma unroll
        for (int c = 0; c < BQ_M; c++) {
            const float* q = new_xyz + (size_t)(cbase + c) * 3;
            float qx = q[0], qy = q[1], qz = q[2];
            qx2[c] = pk2(qx, qx); qy2[c] = pk2(qy, qy); qz2[c] = pk2(qz, qz);
            cnt[c] = 0;
        }

        const float* xb = xyz + (size_t)b * NN * 3;

        for (int tile = seg * SEG_TILES; tile < (seg + 1) * SEG_TILES; tile++) {
            int tilebase = tile * TILE_PTS;
            // stage 1024 points (3072 floats) via 3x LDG.128, negated, swizzled
            #pragma unroll
            for (int j = 0; j < 3; j++) {
                int f0 = (j * 256 + tid) * 4;
                float4 v = *(const float4*)&xb[tilebase * 3 + f0];
                #pragma unroll
                for (int q = 0; q < 4; q++) {
                    int f  = f0 + q;
                    float val = (q == 0) ? v.x : (q == 1) ? v.y : (q == 2) ? v.z : v.w;
                    int pt = f / 3;
                    int d  = f - pt * 3;
                    int fi = swz(pt >> 1) * 2 + (pt & 1);
                    float* dst = (d == 0) ? (float*)sx : (d == 1) ? (float*)sy : (float*)sz;
                    dst[fi] = -val;
                }
            }
            __syncthreads();

            bool active = (cnt[0] < NS) | (cnt[1] < NS) | (cnt[2] < NS) | (cnt[3] < NS);
            if (active) {
                unsigned mk[BQ_M] = {0u, 0u, 0u, 0u};
                #pragma unroll 4
                for (int k = 0; k < 16; k++) {
                    int ph = swz(lane * 16 + k);
                    u64 px = sx[ph], py = sy[ph], pz = sz[ph];
                    #pragma unroll
                    for (int c = 0; c < BQ_M; c++) {
                        u64 dx = addx2(qx2[c], px);     // q - p (points pre-negated)
                        u64 dy = addx2(qy2[c], py);
                        u64 dz = addx2(qz2[c], pz);
                        u64 d2 = fmax2(dx, dx, fmax2(dy, dy, mulx2(dz, dz)));
                        float d0, d1; upk2(d2, d0, d1);
                        mk[c] |= (d0 < R2) ? (1u << (2 * k)) : 0u;
                        mk[c] |= (d1 < R2) ? (2u << (2 * k)) : 0u;
                    }
                }
                // packed prefix: counts for 2 centroids in 16-bit halves, 2 chains ILP
                int pc[BQ_M];
                #pragma unroll
                for (int c = 0; c < BQ_M; c++) pc[c] = __popc(mk[c]);
                unsigned i0 = (unsigned)pc[0] | ((unsigned)pc[1] << 16);
                unsigned i1 = (unsigned)pc[2] | ((unsigned)pc[3] << 16);
                #pragma unroll
                for (int o = 1; o < 32; o <<= 1) {
                    unsigned v0 = __shfl_up_sync(0xffffffffu, i0, o);
                    unsigned v1 = __shfl_up_sync(0xffffffffu, i1, o);
                    if (lane >= o) { i0 += v0; i1 += v1; }
                }
                unsigned t0 = __shfl_sync(0xffffffffu, i0, 31);
                unsigned t1 = __shfl_sync(0xffffffffu, i1, 31);
                int incl[BQ_M]  = { (int)(i0 & 0xffffu), (int)(i0 >> 16),
                                    (int)(i1 & 0xffffu), (int)(i1 >> 16) };
                int total[BQ_M] = { (int)(t0 & 0xffffu), (int)(t0 >> 16),
                                    (int)(t1 & 0xffffu), (int)(t1 >> 16) };
                #pragma unroll
                for (int c = 0; c < BQ_M; c++) {
                    unsigned m = mk[c];
                    int base = cnt[c] + incl[c] - pc[c];
                    if (m && base < NS) {
                        int room = NS - base;
                        if (room > pc[c]) room = pc[c];
                        int pbase = tilebase + lane * 32;
                        int cid = warpId * BQ_M + c;
                        for (int i = 0; i < room; i++) {
                            int bpos = __ffs(m) - 1;
                            m &= m - 1;
                            slist[cid][base + i] = pbase + bpos;
                        }
                    }
                    cnt[c] += total[c];
                }
            }
            __syncthreads();
        }

        __syncwarp();
        #pragma unroll
        for (int c = 0; c < BQ_M; c++) {
            int cid = warpId * BQ_M + c;
            int ci  = cbase + c;
            int cn  = cnt[c] < NS ? cnt[c] : NS;
            if (lane == 0) g_pcnt[ci * SEGS + seg] = cn;
            if (lane < cn) g_pidx[(ci * SEGS + seg) * NS + lane] = slist[cid][lane];
        }
    } else {
        // ---- transpose part: (B,C,N)->(B,N,C), 64x64 tile, ILP-4 float4 ----
        float (*tile)[65] = (float(*)[65])smem_raw;
        int tb = blockIdx.x - NBQ;
        int b  = tb >> 7;
        int n0 = (tb & 127) * 64;
        int cx = threadIdx.x & 15;      // 16 float4 across n
        int cy = threadIdx.x >> 4;      // 16 c rows per pass
        float4 v[4];
        #pragma unroll
        for (int r = 0; r < 4; r++)
            v[r] = *(const float4*)&feat[((size_t)(b * CC + cy + r * 16)) * NN + n0 + cx * 4];
        #pragma unroll
        for (int r = 0; r < 4; r++) {
            tile[cy + r * 16][cx * 4 + 0] = v[r].x;
            tile[cy + r * 16][cx * 4 + 1] = v[r].y;
            tile[cy + r * 16][cx * 4 + 2] = v[r].z;
            tile[cy + r * 16][cx * 4 + 3] = v[r].w;
        }
        __syncthreads();
        #pragma unroll
        for (int r = 0; r < 4; r++) {
            int ny = cy + r * 16;
            float4 w;
            w.x = tile[cx * 4 + 0][ny];
            w.y = tile[cx * 4 + 1][ny];
            w.z = tile[cx * 4 + 2][ny];
            w.w = tile[cx * 4 + 3][ny];
            *(float4*)&g_featT[((size_t)b * NN + n0 + ny) * CC + cx * 4] = w;
        }
    }
}

// ---------------- K2: 128-slot blocks, merge + gather + STG.128 output ---------
__global__ __launch_bounds__(256) void group_kernel(const float* __restrict__ xyz,
                                                    const float* __restrict__ new_xyz,
                                                    const int* __restrict__ fps_idx,
                                                    float* __restrict__ out) {
    __shared__ float sfeat[128][65];
    __shared__ float scent[3][129];
    __shared__ int   sidx[128];

    int b  = blockIdx.y;
    int g0 = blockIdx.x * 128;
    int t  = threadIdx.x;

    if (t < 128) {   // inline merge of 2 per-segment lists (scan-order concat, first 32)
        int gs = g0 + t;
        int p  = gs / NSLOT;
        int sl = gs - p * NSLOT;
        int ci = b * NP + p;
        int v;
        if (sl == 0) {
            v = fps_idx[ci];
        } else {
            int jj = sl - 1;
            int cA = g_pcnt[ci * SEGS + 0];
            int cB = g_pcnt[ci * SEGS + 1];
            const int* A = &g_pidx[(ci * SEGS + 0) * NS];
            const int* Bl = &g_pidx[(ci * SEGS + 1) * NS];
            if (jj < cA)            v = A[jj];
            else if (jj < cA + cB)  v = Bl[jj - cA];
            else                    v = (cA > 0) ? A[0] : ((cB > 0) ? Bl[0] : 0);
        }
        sidx[t] = v;
    }
    __syncthreads();

    if (t < 128) {   // centered xyz for this slot (3 dims)
        int s = t;
        int p = (g0 + s) / NSLOT;
        int pi = sidx[s];
        const float* xp = xyz + ((size_t)b * NN + pi) * 3;
        const float* qp = new_xyz + ((size_t)b * NP + p) * 3;
        #pragma unroll
        for (int dim = 0; dim < 3; dim++)
            scent[dim][s] = xp[dim] - qp[dim];
    }
    {   // warp-per-slot gather: warp w loads rows for slots w*16..w*16+15.
        // Each LDG.64 covers a contiguous 256B row across the warp; 16 rows in flight.
        int w = t >> 5, L = t & 31;
        int base = w * 16;
        const float* fb = g_featT + (size_t)b * NN * CC;
        float2 v[16];
        #pragma unroll
        for (int j = 0; j < 16; j++) {
            int pi = sidx[base + j];            // LDS broadcast (warp-uniform addr)
            v[j] = *(const float2*)(fb + (size_t)pi * CC + 2 * L);
        }
        #pragma unroll
        for (int j = 0; j < 16; j++) {
            sfeat[base + j][2 * L]     = v[j].x;
            sfeat[base + j][2 * L + 1] = v[j].y;
        }
    }
    __syncthreads();

    // output: warp w writes channels w, w+8, ...; one STG.128 per channel,
    // lane L covers slots 4L..4L+3 (contiguous in the slot dimension).
    int w = t >> 5, L = t & 31;
    size_t outbase = (size_t)b * 70 * GPB + g0 + 4 * L;
    #pragma unroll
    for (int it = 0; it < 9; it++) {
        int ch = it * 8 + w;
        if (ch < 70) {
            float4 o;
            if (ch < 6) {
                int r = (ch < 3) ? ch : ch - 3;   // duplicated centered coords
                o.x = scent[r][4 * L];
                o.y = scent[r][4 * L + 1];
                o.z = scent[r][4 * L + 2];
                o.w = scent[r][4 * L + 3];
            } else {
                int c = ch - 6;
                o.x = sfeat[4 * L][c];
                o.y = sfeat[4 * L + 1][c];
                o.z = sfeat[4 * L + 2][c];
                o.w = sfeat[4 * L + 3][c];
            }
            *(float4*)(out + outbase + (size_t)ch * GPB) = o;
        }
    }
}

// ---------------- launch ----------------
extern "C" void kernel_launch(void* const* d_in, const int* in_sizes, int n_in,
                              void* d_out, int out_size) {
    const float* xyz = nullptr;
    const float* new_xyz = nullptr;
    const float* features = nullptr;
    const int*   fps = nullptr;
    for (int i = 0; i < n_in; i++) {
        switch (in_sizes[i]) {
            case BB * NN * 3:  xyz      = (const float*)d_in[i]; break;
            case BB * NP * 3:  new_xyz  = (const float*)d_in[i]; break;
            case BB * CC * NN: features = (const float*)d_in[i]; break;
            case BB * NP:      fps      = (const int*)d_in[i];   break;
        }
    }
    fused_kernel<<<NBQ + NTR, 256>>>(xyz, new_xyz, features);
    group_kernel<<<dim3(GPB / 128, BB), 256>>>(xyz, new_xyz, fps, (float*)d_out);
}